// round 1
// baseline (speedup 1.0000x reference)
#include <cuda_runtime.h>

#define BATCH 64
#define OBJS 2048
#define NTOT (BATCH*OBJS)
#define DIM 256
#define KCH 2
#define CHUNKS 8
#define ROWS_PER_CHUNK (OBJS/CHUNKS)   // 256

// ---------------- scratch (static device globals; fully rewritten each launch) ----
__device__ float g_ctx_part[BATCH][CHUNKS][DIM];
__device__ float g_ctx[BATCH][DIM];
__device__ float g_bias_term[KCH];
__device__ float g_base[NTOT];
__device__ float g_mpart[BATCH][CHUNKS][KCH];
__device__ float g_spart[BATCH][CHUNKS][KCH];
__device__ float g_accpart[BATCH][CHUNKS][DIM][KCH];
__device__ float g_M[BATCH][KCH];
__device__ float g_Sinv[BATCH][KCH];

// ---------------- prep: bias_term[k] = channel_bias[k,:] . att_shared ----------
__global__ void k_prep(const float* __restrict__ att_shared,
                       const float* __restrict__ channel_bias) {
    __shared__ float sh[DIM];
    int t = threadIdx.x;
    float a = att_shared[t];
    for (int k = 0; k < KCH; k++) {
        sh[t] = channel_bias[k * DIM + t] * a;
        __syncthreads();
        for (int off = DIM / 2; off > 0; off >>= 1) {
            if (t < off) sh[t] += sh[t + off];
            __syncthreads();
        }
        if (t == 0) g_bias_term[k] = sh[0];
        __syncthreads();
    }
}

// ---------------- pass 1: partial column sums for ctx ---------------------------
__global__ void __launch_bounds__(256) k_ctx_part(const float* __restrict__ x) {
    int b = blockIdx.x, c = blockIdx.y;
    int t = threadIdx.x;
    int d4 = t & 63;   // which float4 of the row
    int rs = t >> 6;   // row sub-offset 0..3
    const float4* p = (const float4*)x +
        (size_t)(b * OBJS + c * ROWS_PER_CHUNK + rs) * (DIM / 4) + d4;
    float4 s = make_float4(0.f, 0.f, 0.f, 0.f);
#pragma unroll 4
    for (int r = 0; r < ROWS_PER_CHUNK; r += 4) {
        float4 v = p[(size_t)r * (DIM / 4)];
        s.x += v.x; s.y += v.y; s.z += v.z; s.w += v.w;
    }
    __shared__ float4 sh[256];
    sh[t] = s;
    __syncthreads();
    if (rs == 0) {
        float4 v0 = sh[d4], v1 = sh[64 + d4], v2 = sh[128 + d4], v3 = sh[192 + d4];
        float4 o = make_float4(v0.x + v1.x + v2.x + v3.x,
                               v0.y + v1.y + v2.y + v3.y,
                               v0.z + v1.z + v2.z + v3.z,
                               v0.w + v1.w + v2.w + v3.w);
        ((float4*)&g_ctx_part[b][c][0])[d4] = o;
    }
}

__global__ void k_ctx_fin() {
    int b = blockIdx.x, t = threadIdx.x;
    float s = 0.f;
#pragma unroll
    for (int c = 0; c < CHUNKS; c++) s += g_ctx_part[b][c][t];
    g_ctx[b][t] = s * (1.f / OBJS);
}

// ---------------- pass 2: base + online softmax + weighted-pool partials --------
__global__ void __launch_bounds__(256) k_main(const float* __restrict__ x,
                                              const float* __restrict__ att_shared,
                                              const float* __restrict__ att_scale) {
    const int b = blockIdx.x, c = blockIdx.y;
    const int warp = threadIdx.x >> 5, lane = threadIdx.x & 31;

    const float4* a_v = (const float4*)att_shared;
    float4 a0 = a_v[lane];
    float4 a1 = a_v[32 + lane];
    const float4* ctx_v = (const float4*)&g_ctx[b][0];
    float4 c0 = ctx_v[lane];
    float4 c1 = ctx_v[32 + lane];
    const float bias0 = g_bias_term[0], bias1 = g_bias_term[1];
    const float sc0 = att_scale[0], sc1 = att_scale[1];

    const int n0 = b * OBJS + c * ROWS_PER_CHUNK + warp * 32;

    float m0 = -1e30f, m1 = -1e30f, s0 = 0.f, s1 = 0.f;
    float4 A00 = make_float4(0.f, 0.f, 0.f, 0.f), A01 = A00, A10 = A00, A11 = A00;
    float my_base = 0.f;

#pragma unroll 1
    for (int i = 0; i < 32; i++) {
        const float4* row = (const float4*)(x + (size_t)(n0 + i) * DIM);
        float4 x0 = row[lane];
        float4 x1 = row[32 + lane];

        float p, v;
        v = x0.x + c0.x; p  = (v > 0.f ? v : 0.2f * v) * a0.x;
        v = x0.y + c0.y; p += (v > 0.f ? v : 0.2f * v) * a0.y;
        v = x0.z + c0.z; p += (v > 0.f ? v : 0.2f * v) * a0.z;
        v = x0.w + c0.w; p += (v > 0.f ? v : 0.2f * v) * a0.w;
        v = x1.x + c1.x; p += (v > 0.f ? v : 0.2f * v) * a1.x;
        v = x1.y + c1.y; p += (v > 0.f ? v : 0.2f * v) * a1.y;
        v = x1.z + c1.z; p += (v > 0.f ? v : 0.2f * v) * a1.z;
        v = x1.w + c1.w; p += (v > 0.f ? v : 0.2f * v) * a1.w;
#pragma unroll
        for (int o = 16; o > 0; o >>= 1) p += __shfl_xor_sync(0xffffffffu, p, o);
        if (lane == i) my_base = p;

        float l0 = (p + bias0) * sc0;
        float l1 = (p + bias1) * sc1;

        if (l0 > m0) {                       // warp-uniform branch
            float r = __expf(m0 - l0);
            s0 *= r;
            A00.x *= r; A00.y *= r; A00.z *= r; A00.w *= r;
            A01.x *= r; A01.y *= r; A01.z *= r; A01.w *= r;
            m0 = l0;
        }
        float p0 = __expf(l0 - m0);
        s0 += p0;
        A00.x += x0.x * p0; A00.y += x0.y * p0; A00.z += x0.z * p0; A00.w += x0.w * p0;
        A01.x += x1.x * p0; A01.y += x1.y * p0; A01.z += x1.z * p0; A01.w += x1.w * p0;

        if (l1 > m1) {
            float r = __expf(m1 - l1);
            s1 *= r;
            A10.x *= r; A10.y *= r; A10.z *= r; A10.w *= r;
            A11.x *= r; A11.y *= r; A11.z *= r; A11.w *= r;
            m1 = l1;
        }
        float p1 = __expf(l1 - m1);
        s1 += p1;
        A10.x += x0.x * p1; A10.y += x0.y * p1; A10.z += x0.z * p1; A10.w += x0.w * p1;
        A11.x += x1.x * p1; A11.y += x1.y * p1; A11.z += x1.z * p1; A11.w += x1.w * p1;
    }
    g_base[n0 + lane] = my_base;

    // ---- block combine over 8 warps ----
    __shared__ float shm[KCH][8], shs[KCH][8];
    __shared__ float shacc[8][32][16];
    if (lane == 0) { shm[0][warp] = m0; shm[1][warp] = m1; }
    __syncthreads();
    float M0 = shm[0][0], M1 = shm[1][0];
#pragma unroll
    for (int w = 1; w < 8; w++) {
        M0 = fmaxf(M0, shm[0][w]);
        M1 = fmaxf(M1, shm[1][w]);
    }
    float f0 = __expf(m0 - M0), f1 = __expf(m1 - M1);
    if (lane == 0) { shs[0][warp] = s0 * f0; shs[1][warp] = s1 * f1; }
    // slot layout: [k*8 + half*4 + comp]
    float* sa = &shacc[warp][lane][0];
    sa[0] = A00.x * f0; sa[1]  = A00.y * f0; sa[2]  = A00.z * f0; sa[3]  = A00.w * f0;
    sa[4] = A01.x * f0; sa[5]  = A01.y * f0; sa[6]  = A01.z * f0; sa[7]  = A01.w * f0;
    sa[8] = A10.x * f1; sa[9]  = A10.y * f1; sa[10] = A10.z * f1; sa[11] = A10.w * f1;
    sa[12]= A11.x * f1; sa[13] = A11.y * f1; sa[14] = A11.z * f1; sa[15] = A11.w * f1;
    __syncthreads();

    int t = threadIdx.x;
#pragma unroll
    for (int o = t; o < DIM * KCH; o += 256) {
        int d = o >> 1, k = o & 1;
        int lane_i = (d & 127) >> 2;
        int slot = k * 8 + ((d >> 7) << 2) + (d & 3);
        float sum = 0.f;
#pragma unroll
        for (int w = 0; w < 8; w++) sum += shacc[w][lane_i][slot];
        g_accpart[b][c][d][k] = sum;
    }
    if (t == 0) {
        float S0 = 0.f, S1 = 0.f;
#pragma unroll
        for (int w = 0; w < 8; w++) { S0 += shs[0][w]; S1 += shs[1][w]; }
        g_mpart[b][c][0] = M0; g_mpart[b][c][1] = M1;
        g_spart[b][c][0] = S0; g_spart[b][c][1] = S1;
    }
}

// ---------------- combine chunk partials -> scene_features, M, 1/S --------------
__global__ void k_combine(float* __restrict__ out) {
    int b = blockIdx.x, t = threadIdx.x;   // t = d
    float M[KCH], S[KCH];
#pragma unroll
    for (int k = 0; k < KCH; k++) {
        float mm = g_mpart[b][0][k];
#pragma unroll
        for (int c = 1; c < CHUNKS; c++) mm = fmaxf(mm, g_mpart[b][c][k]);
        M[k] = mm;
        float ss = 0.f;
#pragma unroll
        for (int c = 0; c < CHUNKS; c++)
            ss += g_spart[b][c][k] * __expf(g_mpart[b][c][k] - mm);
        S[k] = ss;
    }
#pragma unroll
    for (int k = 0; k < KCH; k++) {
        float acc = 0.f;
#pragma unroll
        for (int c = 0; c < CHUNKS; c++)
            acc += g_accpart[b][c][t][k] * __expf(g_mpart[b][c][k] - M[k]);
        out[((size_t)b * DIM + t) * KCH + k] = acc / S[k];
    }
    if (t < KCH) {
        g_M[b][t] = M[t];
        g_Sinv[b][t] = 1.f / S[t];
    }
}

// ---------------- attention weights output --------------------------------------
__global__ void __launch_bounds__(256) k_weights(float* __restrict__ outw,
                                                 const float* __restrict__ att_scale) {
    int n = blockIdx.x * 256 + threadIdx.x;
    int b = n >> 11;  // /OBJS
    float base = g_base[n];
    float2 w;
    w.x = __expf((base + g_bias_term[0]) * att_scale[0] - g_M[b][0]) * g_Sinv[b][0];
    w.y = __expf((base + g_bias_term[1]) * att_scale[1] - g_M[b][1]) * g_Sinv[b][1];
    ((float2*)outw)[n] = w;
}

// ---------------- launch ---------------------------------------------------------
extern "C" void kernel_launch(void* const* d_in, const int* in_sizes, int n_in,
                              void* d_out, int out_size) {
    const float* x          = (const float*)d_in[0];
    // d_in[1] = num_objs (int32) — uniform OBJS per setup; unused
    const float* att_shared = (const float*)d_in[2];
    const float* att_scale  = (const float*)d_in[3];
    const float* chan_bias  = (const float*)d_in[4];
    float* out = (float*)d_out;
    float* out_feat = out;                               // [B, D, K]
    float* out_w    = out + (size_t)BATCH * DIM * KCH;   // [N, K]

    k_prep<<<1, DIM>>>(att_shared, chan_bias);
    k_ctx_part<<<dim3(BATCH, CHUNKS), 256>>>(x);
    k_ctx_fin<<<BATCH, DIM>>>();
    k_main<<<dim3(BATCH, CHUNKS), 256>>>(x, att_shared, att_scale);
    k_combine<<<BATCH, DIM>>>(out_feat);
    k_weights<<<NTOT / 256, 256>>>(out_w, att_scale);
}